// round 15
// baseline (speedup 1.0000x reference)
#include <cuda_runtime.h>
#include <math.h>

// Problem constants (fixed by the reference build)
#define MM   4096      // checks
#define NN   8192      // variables
#define BB   256       // batch
#define EE   32768     // edges  (NN * DV)
#define N_ITERS 10
#define ALPHA_C 0.8f
#define CLAMP_V 20.0f
#define PAD_BIG_C 1.0e6f

// ---------------- static device scratch (no allocations allowed) -----------
// vtc: CHECK-major padded rows  [c*32 + p][B]  — checkupd reads sequentially
// ctv: VAR-major rows           [v*4  + s][B]  — varsum reads sequentially
__device__ float g_vtc  [MM * 32 * BB];  // clamped var->check messages
__device__ float g_ctv  [NN * 4 * BB];   // check->var messages
__device__ float g_llr_t[NN * BB];       // transposed channel LLR, [N,B]
__device__ float g_ssign[MM * BB];       // 1-2*syndrome, [M,B]
__device__ float g_hard [NN * BB];       // hard decisions, [N,B] (for parity)
__device__ int   g_deg  [MM];            // check degrees
__device__ int   g_ce   [MM * 32];       // check slot -> var-major eid (v*4+s)
__device__ int   g_cv   [MM * 32];       // check slot -> var id (parity)
__device__ int   g_vs   [NN * 4];        // var slot -> check-major eid (c*32+p)
__device__ int   g_padcm;                // check-major eid of reference edge 0

// ---------------- helpers ----------------------------------------------------
__device__ __forceinline__ float clampv(float x) {
    return fminf(fmaxf(x, -CLAMP_V), CLAMP_V);
}

// ---------------- kernels ---------------------------------------------------
// Device globals referenced only from device code (host shadow is not a dev ptr).

// Prep: degrees + both translation tables + pad position. MUST run before
// k_tr_llr (which uses g_vs). Each edge belongs to exactly one check, so
// every g_vs slot is written exactly once.
__global__ void k_prep(const float* __restrict__ check_mask,
                       const int* __restrict__ check_adj,
                       const int* __restrict__ var_idx,
                       const int* __restrict__ var_adj,
                       int max_dc)
{
    int c = blockIdx.x * blockDim.x + threadIdx.x;
    if (c >= MM) return;
    const float* m   = check_mask + (size_t)c * max_dc;
    const int*   adj = check_adj  + (size_t)c * max_dc;
    int d = 0;
    for (int j = 0; j < max_dc; j++) {
        if (__ldg(m + j) != 0.0f) {
            int e = __ldg(adj + j);
            int v = __ldg(var_idx + e);
            int s = 0;
            #pragma unroll
            for (int q = 0; q < 4; q++)
                if (__ldg(var_adj + v * 4 + q) == e) s = q;
            g_ce[c * 32 + d] = v * 4 + s;
            g_cv[c * 32 + d] = v;
            g_vs[v * 4 + s]  = c * 32 + d;
            if (e == 0) g_padcm = c * 32 + d;   // reference edge 0 position
            d++;
        }
    }
    g_deg[c] = d;
}

// Transpose llr [B,N] -> g_llr_t [N,B]; seed vtc (iter0 ctv==0 so
// vtc = clamp(llr)) scattered into check-major rows via g_vs.
__global__ void k_tr_llr(const float* __restrict__ in)
{
    __shared__ float tile[32][33];
    int c0 = blockIdx.x * 32;   // N tile
    int r0 = blockIdx.y * 32;   // B tile
    int c = c0 + threadIdx.x;
    #pragma unroll
    for (int i = 0; i < 32; i += 8) {
        int r = r0 + threadIdx.y + i;
        tile[threadIdx.y + i][threadIdx.x] = in[(size_t)r * NN + c];
    }
    __syncthreads();
    int oc = r0 + threadIdx.x;            // batch index
    #pragma unroll
    for (int i = 0; i < 32; i += 8) {
        int v = c0 + threadIdx.y + i;     // var index (uniform per warp)
        float x = tile[threadIdx.x][threadIdx.y + i];
        g_llr_t[(size_t)v * BB + oc] = x;
        float cv = clampv(x);
        int4 ds = __ldg((const int4*)g_vs + v);
        g_vtc[(size_t)ds.x * BB + oc] = cv;
        g_vtc[(size_t)ds.y * BB + oc] = cv;
        g_vtc[(size_t)ds.z * BB + oc] = cv;
        g_vtc[(size_t)ds.w * BB + oc] = cv;
    }
}

// Transpose syndrome [B,M] -> g_ssign [M,B] with 1-2x.
__global__ void k_tr_syn(const float* __restrict__ in)
{
    __shared__ float tile[32][33];
    int c0 = blockIdx.x * 32;
    int r0 = blockIdx.y * 32;
    int c = c0 + threadIdx.x;
    #pragma unroll
    for (int i = 0; i < 32; i += 8) {
        int r = r0 + threadIdx.y + i;
        tile[threadIdx.y + i][threadIdx.x] = in[(size_t)r * MM + c];
    }
    __syncthreads();
    int oc = r0 + threadIdx.x;
    #pragma unroll
    for (int i = 0; i < 32; i += 8) {
        int orow = c0 + threadIdx.y + i;
        g_ssign[(size_t)orow * BB + oc] =
            1.0f - 2.0f * tile[threadIdx.x][threadIdx.y + i];
    }
}

// Check side: R5 numerics exactly. Reads vtc rows SEQUENTIALLY (check-major),
// scatter-writes ctv into var-major rows via g_ce.
// Block = 256 threads = 4 checks x 64 float4-lanes.
__global__ void __launch_bounds__(256) k_checkupd()
{
    int t = threadIdx.x;
    int c = blockIdx.x * 4 + (t >> 6);
    int j = t & 63;
    int deg = g_deg[c];
    if (deg == 0) return;
    const float* vrow = g_vtc + (size_t)c * 32 * BB;   // sequential rows

    float4 sg = ((const float4*)(g_ssign + (size_t)c * BB))[j];
    float4 m1, m2;
    if (deg == 1) {
        // reference pads with edge 0: seed = |vtc(edge0)| + 1e6 (clamped)
        float4 p0 = ((const float4*)(g_vtc + (size_t)g_padcm * BB))[j];
        m1.x = fabsf(p0.x) + PAD_BIG_C;
        m1.y = fabsf(p0.y) + PAD_BIG_C;
        m1.z = fabsf(p0.z) + PAD_BIG_C;
        m1.w = fabsf(p0.w) + PAD_BIG_C;
    } else {
        m1.x = m1.y = m1.z = m1.w = 1.0e30f;   // pad can never win for deg>=2
    }
    m2 = m1;

    // pass 1: sign product + two smallest magnitudes (sequential reads)
    #pragma unroll 8
    for (int p = 0; p < deg; p++) {
        float4 x = ((const float4*)(vrow + (size_t)p * BB))[j];
        if (x.x < 0.0f) sg.x = -sg.x;
        if (x.y < 0.0f) sg.y = -sg.y;
        if (x.z < 0.0f) sg.z = -sg.z;
        if (x.w < 0.0f) sg.w = -sg.w;
        float a;
        a = fabsf(x.x); if (a < m1.x) { m2.x = m1.x; m1.x = a; } else if (a < m2.x) m2.x = a;
        a = fabsf(x.y); if (a < m1.y) { m2.y = m1.y; m1.y = a; } else if (a < m2.y) m2.y = a;
        a = fabsf(x.z); if (a < m1.z) { m2.z = m1.z; m1.z = a; } else if (a < m2.z) m2.z = a;
        a = fabsf(x.w); if (a < m1.w) { m2.w = m1.w; m1.w = a; } else if (a < m2.w) m2.w = a;
    }

    // pass 2: reload (L1-hot within launch), scatter-write new messages
    const int* ce = g_ce + c * 32;
    #pragma unroll 8
    for (int p = 0; p < deg; p++) {
        float4 x = ((const float4*)(vrow + (size_t)p * BB))[j];
        float4 out;
        {
            float a = fabsf(x.x);
            float m = (fabsf(a - m1.x) < 1e-9f) ? m2.x : m1.x;
            out.x = ALPHA_C * sg.x * ((x.x < 0.0f) ? -m : m);
        }
        {
            float a = fabsf(x.y);
            float m = (fabsf(a - m1.y) < 1e-9f) ? m2.y : m1.y;
            out.y = ALPHA_C * sg.y * ((x.y < 0.0f) ? -m : m);
        }
        {
            float a = fabsf(x.z);
            float m = (fabsf(a - m1.z) < 1e-9f) ? m2.z : m1.z;
            out.z = ALPHA_C * sg.z * ((x.z < 0.0f) ? -m : m);
        }
        {
            float a = fabsf(x.w);
            float m = (fabsf(a - m1.w) < 1e-9f) ? m2.w : m1.w;
            out.w = ALPHA_C * sg.w * ((x.w < 0.0f) ? -m : m);
        }
        ((float4*)(g_ctv + (size_t)ce[p] * BB))[j] = out;   // scatter
    }
}

// Var side: R5 numerics exactly. Reads its 4 ctv rows SEQUENTIALLY (var-major,
// one 4 KB block), scatter-writes vtc into check-major rows via g_vs.
// Block = 256 threads = 4 vars x 64 float4-lanes.
__global__ void __launch_bounds__(256) k_varsum()
{
    int t = threadIdx.x;
    int v = blockIdx.x * 4 + (t >> 6);
    int j = t & 63;
    const float* crow = g_ctv + (size_t)v * 4 * BB;    // sequential rows
    float4 a = ((const float4*)(crow))[j];
    float4 b = ((const float4*)(crow + BB))[j];
    float4 c = ((const float4*)(crow + 2 * BB))[j];
    float4 d = ((const float4*)(crow + 3 * BB))[j];
    float4 l = ((const float4*)(g_llr_t + (size_t)v * BB))[j];
    float4 s;   // EXACT reference order
    s.x = l.x + (((a.x + b.x) + c.x) + d.x);
    s.y = l.y + (((a.y + b.y) + c.y) + d.y);
    s.z = l.z + (((a.z + b.z) + c.z) + d.z);
    s.w = l.w + (((a.w + b.w) + c.w) + d.w);

    int4 ds = __ldg((const int4*)g_vs + v);
    float4 o;
    o.x = clampv(s.x - a.x); o.y = clampv(s.y - a.y);
    o.z = clampv(s.z - a.z); o.w = clampv(s.w - a.w);
    ((float4*)(g_vtc + (size_t)ds.x * BB))[j] = o;
    o.x = clampv(s.x - b.x); o.y = clampv(s.y - b.y);
    o.z = clampv(s.z - b.z); o.w = clampv(s.w - b.w);
    ((float4*)(g_vtc + (size_t)ds.y * BB))[j] = o;
    o.x = clampv(s.x - c.x); o.y = clampv(s.y - c.y);
    o.z = clampv(s.z - c.z); o.w = clampv(s.w - c.w);
    ((float4*)(g_vtc + (size_t)ds.z * BB))[j] = o;
    o.x = clampv(s.x - d.x); o.y = clampv(s.y - d.y);
    o.z = clampv(s.z - d.z); o.w = clampv(s.w - d.w);
    ((float4*)(g_vtc + (size_t)ds.w * BB))[j] = o;
}

// Final (fused): total_llr = llr + sum(ctv) with sequential ctv reads;
// marginals + hard to d_out [B,N]; hard also to g_hard [N,B];
// block (0,0) initializes conv to 1.
__global__ void k_out(float* __restrict__ out_marg,
                      float* __restrict__ out_hard,
                      float* __restrict__ conv)
{
    __shared__ float tile[32][33];
    int c0 = blockIdx.x * 32;   // batch tile
    int r0 = blockIdx.y * 32;   // var tile
    int c = c0 + threadIdx.x;   // batch index
    if (blockIdx.x == 0 && blockIdx.y == 0)
        conv[threadIdx.y * 32 + threadIdx.x] = 1.0f;
    #pragma unroll
    for (int i = 0; i < 32; i += 8) {
        int v = r0 + threadIdx.y + i;      // uniform per warp
        const float* crow = g_ctv + (size_t)v * 4 * BB;
        float a  = crow[c];
        float b  = crow[BB + c];
        float d0 = crow[2 * BB + c];
        float d1 = crow[3 * BB + c];
        float l = g_llr_t[(size_t)v * BB + c];
        float tt = l + (((a + b) + d0) + d1);
        tile[threadIdx.y + i][threadIdx.x] = tt;
        float marg = 1.0f / (1.0f + expf(tt));
        g_hard[(size_t)v * BB + c] = (marg > 0.5f) ? 1.0f : 0.0f;
    }
    __syncthreads();
    int oc = r0 + threadIdx.x;            // var index in output
    #pragma unroll
    for (int i = 0; i < 32; i += 8) {
        int orow = c0 + threadIdx.y + i;  // batch index in output
        float tt = tile[threadIdx.x][threadIdx.y + i];
        float marg = 1.0f / (1.0f + expf(tt));
        size_t oi = (size_t)orow * NN + oc;
        out_marg[oi] = marg;
        out_hard[oi] = (marg > 0.5f) ? 1.0f : 0.0f;
    }
}

// Parity per (check, batch-quad): mismatch -> converged[b] = 0.
__global__ void k_parity(float* __restrict__ conv)
{
    int t = threadIdx.x;
    int c = blockIdx.x * 4 + (t >> 6);
    int j = t & 63;
    int deg = g_deg[c];
    const int* cv = g_cv + c * 32;
    int p0 = 0, p1 = 0, p2 = 0, p3 = 0;
    for (int p = 0; p < deg; p++) {
        int v = cv[p];
        float4 h = ((const float4*)(g_hard + (size_t)v * BB))[j];
        p0 += (int)h.x; p1 += (int)h.y; p2 += (int)h.z; p3 += (int)h.w;
    }
    float4 sg = ((const float4*)(g_ssign + (size_t)c * BB))[j];
    if ((p0 & 1) != (sg.x < 0.0f ? 1 : 0)) conv[j * 4 + 0] = 0.0f;
    if ((p1 & 1) != (sg.y < 0.0f ? 1 : 0)) conv[j * 4 + 1] = 0.0f;
    if ((p2 & 1) != (sg.z < 0.0f ? 1 : 0)) conv[j * 4 + 2] = 0.0f;
    if ((p3 & 1) != (sg.w < 0.0f ? 1 : 0)) conv[j * 4 + 3] = 0.0f;
}

// ---------------- launch ----------------------------------------------------

extern "C" void kernel_launch(void* const* d_in, const int* in_sizes, int n_in,
                              void* d_out, int out_size)
{
    const float* syndrome   = (const float*)d_in[0];   // [B, M]
    const float* llr        = (const float*)d_in[1];   // [B, N]
    const int*   var_adj    = (const int*)  d_in[2];   // [N, 4]
    const int*   check_adj  = (const int*)  d_in[4];   // [M, max_dc]
    const float* check_mask = (const float*)d_in[5];   // [M, max_dc]
    const int*   var_idx    = (const int*)  d_in[6];   // [E]

    const int max_dc = in_sizes[4] / MM;   // <= 32 for this code family
    float* out = (float*)d_out;
    size_t bn = (size_t)BB * NN;
    float* out_marg = out;            // [B, N]
    float* out_hard = out + bn;       // [B, N]
    float* out_conv = out + 2 * bn;   // [B]

    dim3 tb(32, 8);
    // prep FIRST: k_tr_llr consumes g_vs
    k_prep<<<(MM + 255) / 256, 256>>>(check_mask, check_adj, var_idx,
                                      var_adj, max_dc);
    k_tr_llr<<<dim3(NN / 32, BB / 32), tb>>>(llr);       // llr_t + iter0 vtc
    k_tr_syn<<<dim3(MM / 32, BB / 32), tb>>>(syndrome);  // ssign

    k_checkupd<<<MM / 4, 256>>>();
    for (int it = 1; it < N_ITERS; it++) {
        k_varsum<<<NN / 4, 256>>>();
        k_checkupd<<<MM / 4, 256>>>();
    }

    k_out<<<dim3(BB / 32, NN / 32), tb>>>(out_marg, out_hard, out_conv);
    k_parity<<<MM / 4, 256>>>(out_conv);
}